// round 2
// baseline (speedup 1.0000x reference)
#include <cuda_runtime.h>

#define NN   50000
#define FIN  256
#define HD   128
#define SS   50
#define GG   1000          // NN/SS
#define EMAX 1600000
#define NBLK ((NN + 255) / 256)   // 196

// ---------------- scratch (static device globals; no allocation) ----------------
__device__ __align__(16) int   g_deg[NN];
__device__ __align__(16) float g_dinv[NN];
__device__ __align__(16) int   g_rowptr[NN + 1];
__device__ __align__(16) int   g_fill[NN];
__device__ __align__(16) int   g_srcs[EMAX];
__device__ __align__(16) float g_norm[EMAX];
__device__ __align__(16) float g_xw[NN * HD];
__device__ __align__(16) float g_h1[NN * HD];
__device__ __align__(16) float g_hw[NN * HD];

// ---------------- CSR build ----------------
__global__ void k_zero_deg() {
    int i = blockIdx.x * blockDim.x + threadIdx.x;
    if (i < NN) g_deg[i] = 0;
}

__global__ void k_count(const int* __restrict__ dst, int Ecnt) {
    int e = blockIdx.x * blockDim.x + threadIdx.x;
    if (e < Ecnt) atomicAdd(&g_deg[dst[e]], 1);
}

// single block, 1024 threads: dinv + full inclusive scan + fill-cursor init
__global__ void k_scan_all() {
    __shared__ int warp_tot[32];
    int tid = threadIdx.x;
    int lane = tid & 31, wid = tid >> 5;
    int carry = 0;

    for (int base = 0; base < NN; base += 1024) {
        int i = base + tid;
        int d = (i < NN) ? g_deg[i] : 0;
        if (i < NN) g_dinv[i] = rsqrtf((float)d + 1.0f);   // +1 self-loop

        // warp inclusive scan
        int v = d;
        #pragma unroll
        for (int o = 1; o < 32; o <<= 1) {
            int t = __shfl_up_sync(0xffffffffu, v, o);
            if (lane >= o) v += t;
        }
        if (lane == 31) warp_tot[wid] = v;
        __syncthreads();
        if (wid == 0) {
            int w = warp_tot[lane];
            #pragma unroll
            for (int o = 1; o < 32; o <<= 1) {
                int t = __shfl_up_sync(0xffffffffu, w, o);
                if (lane >= o) w += t;
            }
            warp_tot[lane] = w;
        }
        __syncthreads();
        int incl = v + (wid > 0 ? warp_tot[wid - 1] : 0) + carry;
        if (i < NN) {
            g_rowptr[i + 1] = incl;
            g_fill[i] = incl - d;      // exclusive prefix = rowptr[i]
        }
        if (i == 0) g_rowptr[0] = 0;
        carry += warp_tot[31];
        __syncthreads();               // protect warp_tot before next chunk
    }
}

__global__ void k_fill(const int* __restrict__ src, const int* __restrict__ dst, int Ecnt) {
    int e = blockIdx.x * blockDim.x + threadIdx.x;
    if (e < Ecnt) {
        int s = src[e], d = dst[e];
        int p = atomicAdd(&g_fill[d], 1);
        g_srcs[p] = s;
        g_norm[p] = g_dinv[s] * g_dinv[d];
    }
}

// ---------------- generic GEMM: C[M,128] = A[M,K] @ B[K,128] ----------------
// BM=64, BN=128, BK=16; 256 threads, each computes 8x4.
__global__ void gemm_k(const float* __restrict__ A, const float* __restrict__ B,
                       float* __restrict__ C, int M, int K) {
    __shared__ float As[64][16];
    __shared__ float Bs[16][128];
    int tid = threadIdx.x;
    int tx = tid & 31, ty = tid >> 5;
    int r0 = blockIdx.x * 64;

    float acc[8][4];
    #pragma unroll
    for (int i = 0; i < 8; i++)
        #pragma unroll
        for (int j = 0; j < 4; j++) acc[i][j] = 0.0f;

    for (int kt = 0; kt < K; kt += 16) {
        {
            int l = tid * 4;
            int row = l >> 4, col = l & 15;
            int gr = r0 + row;
            float4 v = make_float4(0.f, 0.f, 0.f, 0.f);
            if (gr < M) v = *(const float4*)&A[(long)gr * K + kt + col];
            *(float4*)&As[row][col] = v;
        }
        #pragma unroll
        for (int it = 0; it < 2; it++) {
            int l = (tid + it * 256) * 4;
            int row = l >> 7, col = l & 127;
            *(float4*)&Bs[row][col] = *(const float4*)&B[(kt + row) * 128 + col];
        }
        __syncthreads();

        #pragma unroll
        for (int k = 0; k < 16; k++) {
            float4 bv = *(float4*)&Bs[k][tx * 4];
            #pragma unroll
            for (int i = 0; i < 8; i++) {
                float a = As[ty * 8 + i][k];
                acc[i][0] = fmaf(a, bv.x, acc[i][0]);
                acc[i][1] = fmaf(a, bv.y, acc[i][1]);
                acc[i][2] = fmaf(a, bv.z, acc[i][2]);
                acc[i][3] = fmaf(a, bv.w, acc[i][3]);
            }
        }
        __syncthreads();
    }

    #pragma unroll
    for (int i = 0; i < 8; i++) {
        int r = r0 + ty * 8 + i;
        if (r < M) {
            float4 v = make_float4(acc[i][0], acc[i][1], acc[i][2], acc[i][3]);
            *(float4*)&C[(long)r * 128 + tx * 4] = v;
        }
    }
}

// ---------------- GCN aggregation, MLP-4 unrolled gather ----------------
// one warp per node, float4 per lane; O[n] = sum norm*T[s] + dinv(n)^2*T[n] + b
__global__ void agg_k(const float* __restrict__ T, const float* __restrict__ bias,
                      float* __restrict__ O, int relu) {
    int warp = threadIdx.x >> 5, lane = threadIdx.x & 31;
    int node = blockIdx.x * 8 + warp;
    if (node >= NN) return;

    const float4* __restrict__ Tv = (const float4*)T;
    float di = g_dinv[node];
    float w0 = di * di;
    float4 a = Tv[node * 32 + lane];
    float4 acc;
    acc.x = w0 * a.x; acc.y = w0 * a.y; acc.z = w0 * a.z; acc.w = w0 * a.w;

    int b = g_rowptr[node], e = g_rowptr[node + 1];
    int j = b;
    // 4x unrolled: batch index/weight loads, then 4 gathers in flight
    for (; j + 4 <= e; j += 4) {
        int s0 = __ldg(&g_srcs[j + 0]);
        int s1 = __ldg(&g_srcs[j + 1]);
        int s2 = __ldg(&g_srcs[j + 2]);
        int s3 = __ldg(&g_srcs[j + 3]);
        float n0 = __ldg(&g_norm[j + 0]);
        float n1 = __ldg(&g_norm[j + 1]);
        float n2 = __ldg(&g_norm[j + 2]);
        float n3 = __ldg(&g_norm[j + 3]);
        float4 v0 = Tv[s0 * 32 + lane];
        float4 v1 = Tv[s1 * 32 + lane];
        float4 v2 = Tv[s2 * 32 + lane];
        float4 v3 = Tv[s3 * 32 + lane];
        acc.x = fmaf(n0, v0.x, acc.x); acc.y = fmaf(n0, v0.y, acc.y);
        acc.z = fmaf(n0, v0.z, acc.z); acc.w = fmaf(n0, v0.w, acc.w);
        acc.x = fmaf(n1, v1.x, acc.x); acc.y = fmaf(n1, v1.y, acc.y);
        acc.z = fmaf(n1, v1.z, acc.z); acc.w = fmaf(n1, v1.w, acc.w);
        acc.x = fmaf(n2, v2.x, acc.x); acc.y = fmaf(n2, v2.y, acc.y);
        acc.z = fmaf(n2, v2.z, acc.z); acc.w = fmaf(n2, v2.w, acc.w);
        acc.x = fmaf(n3, v3.x, acc.x); acc.y = fmaf(n3, v3.y, acc.y);
        acc.z = fmaf(n3, v3.z, acc.z); acc.w = fmaf(n3, v3.w, acc.w);
    }
    for (; j < e; j++) {
        int s = __ldg(&g_srcs[j]);
        float w = __ldg(&g_norm[j]);
        float4 v = Tv[s * 32 + lane];
        acc.x = fmaf(w, v.x, acc.x);
        acc.y = fmaf(w, v.y, acc.y);
        acc.z = fmaf(w, v.z, acc.z);
        acc.w = fmaf(w, v.w, acc.w);
    }
    float4 bb = ((const float4*)bias)[lane];
    acc.x += bb.x; acc.y += bb.y; acc.z += bb.z; acc.w += bb.w;
    if (relu) {
        acc.x = fmaxf(acc.x, 0.f); acc.y = fmaxf(acc.y, 0.f);
        acc.z = fmaxf(acc.z, 0.f); acc.w = fmaxf(acc.w, 0.f);
    }
    ((float4*)O)[node * 32 + lane] = acc;
}

// ---------------- pooled head: out[g,j] = sum_k emb[g*6400+k]*Wl[k,j] + bl[j] ----------------
__global__ void pool_k(const float* __restrict__ emb, const float* __restrict__ Wl,
                       const float* __restrict__ bl, float* __restrict__ out) {
    __shared__ float sW[32][128];
    __shared__ float sE[8][33];
    int tid = threadIdx.x;
    int g0 = blockIdx.x * 8;
    int jj = tid & 127, half = tid >> 7;

    float acc[4] = {0.f, 0.f, 0.f, 0.f};

    for (int k0 = 0; k0 < SS * HD; k0 += 32) {
        #pragma unroll
        for (int it = 0; it < 4; it++) {
            int l = (tid + it * 256) * 4;
            int row = l >> 7, col = l & 127;
            *(float4*)&sW[row][col] = *(const float4*)&Wl[(k0 + row) * 128 + col];
        }
        {
            int r = tid >> 5, c = tid & 31;
            sE[r][c] = emb[(g0 + r) * 6400 + k0 + c];
        }
        __syncthreads();

        #pragma unroll
        for (int kk = 0; kk < 32; kk++) {
            float w = sW[kk][jj];
            #pragma unroll
            for (int gg = 0; gg < 4; gg++)
                acc[gg] = fmaf(sE[half * 4 + gg][kk], w, acc[gg]);
        }
        __syncthreads();
    }

    float bv = bl[jj];
    #pragma unroll
    for (int gg = 0; gg < 4; gg++)
        out[(g0 + half * 4 + gg) * 128 + jj] = acc[gg] + bv;
}

// ---------------- launch ----------------
extern "C" void kernel_launch(void* const* d_in, const int* in_sizes, int n_in,
                              void* d_out, int out_size) {
    const float* x  = (const float*)d_in[0];
    const float* W1 = (const float*)d_in[1];
    const float* b1 = (const float*)d_in[2];
    const float* W2 = (const float*)d_in[3];
    const float* b2 = (const float*)d_in[4];
    const float* Wl = (const float*)d_in[5];
    const float* bl = (const float*)d_in[6];
    const int*   ei = (const int*)d_in[7];

    int Ecnt = in_sizes[7] / 2;
    const int* src = ei;
    const int* dst = ei + Ecnt;

    float* out = (float*)d_out;            // [1000,128]
    float* emb = out + GG * HD;            // [50000,128]

    int eb = (Ecnt + 255) / 256;

    // CSR build (4 launches)
    k_zero_deg<<<NBLK, 256>>>();
    k_count<<<eb, 256>>>(dst, Ecnt);
    k_scan_all<<<1, 1024>>>();
    k_fill<<<eb, 256>>>(src, dst, Ecnt);

    // layer 1
    gemm_k<<<(NN + 63) / 64, 256>>>(x, W1, g_xw, NN, FIN);
    agg_k<<<(NN + 7) / 8, 256>>>(g_xw, b1, g_h1, 1);

    // layer 2
    gemm_k<<<(NN + 63) / 64, 256>>>(g_h1, W2, g_hw, NN, HD);
    agg_k<<<(NN + 7) / 8, 256>>>(g_hw, b2, emb, 0);

    // pooled head
    pool_k<<<(GG + 7) / 8, 256>>>(emb, Wl, bl, out);
}

// round 5
// speedup vs baseline: 1.0047x; 1.0047x over previous
#include <cuda_runtime.h>

#define NN   50000
#define FIN  256
#define HD   128
#define SS   50
#define GG   1000          // NN/SS
#define EMAX 1600000
#define NBLK ((NN + 255) / 256)   // 196

// ---------------- scratch (static device globals; no allocation) ----------------
__device__ __align__(16) int   g_deg[NN];
__device__ __align__(16) float g_dinv[NN];
__device__ __align__(16) int   g_rowptr[NN + 1];
__device__ __align__(16) int   g_fill[NN];
__device__ __align__(16) int   g_srcs[EMAX];
__device__ __align__(16) float g_norm[EMAX];
__device__ __align__(16) float g_xw[NN * HD];
__device__ __align__(16) float g_h1[NN * HD];
__device__ __align__(16) float g_hw[NN * HD];
__device__ __align__(16) int   g_part[256];

// ---------------- CSR build ----------------
__global__ void k_zero_deg() {
    int i = blockIdx.x * blockDim.x + threadIdx.x;
    if (i < NN) g_deg[i] = 0;
}

__global__ void k_count(const int* __restrict__ dst, int Ecnt) {
    int e = blockIdx.x * blockDim.x + threadIdx.x;
    if (e < Ecnt) atomicAdd(&g_deg[dst[e]], 1);
}

__global__ void k_dinv() {
    int i = blockIdx.x * blockDim.x + threadIdx.x;
    if (i < NN) g_dinv[i] = rsqrtf((float)g_deg[i] + 1.0f);  // +1 self-loop
}

__global__ void k_scan1() {
    __shared__ int sh[256];
    int tid = threadIdx.x;
    int i = blockIdx.x * 256 + tid;
    int v = (i < NN) ? g_deg[i] : 0;
    sh[tid] = v;
    __syncthreads();
    #pragma unroll
    for (int o = 1; o < 256; o <<= 1) {
        int t = (tid >= o) ? sh[tid - o] : 0;
        __syncthreads();
        sh[tid] += t;
        __syncthreads();
    }
    if (i < NN) g_rowptr[i + 1] = sh[tid];
    if (tid == 255) g_part[blockIdx.x] = sh[255];
}

__global__ void k_scan2() {
    __shared__ int sh[256];
    int tid = threadIdx.x;
    int v = (tid < NBLK) ? g_part[tid] : 0;
    sh[tid] = v;
    __syncthreads();
    #pragma unroll
    for (int o = 1; o < 256; o <<= 1) {
        int t = (tid >= o) ? sh[tid - o] : 0;
        __syncthreads();
        sh[tid] += t;
        __syncthreads();
    }
    g_part[tid] = sh[tid];
}

// finalize rowptr and init fill cursor in one kernel
__global__ void k_scan3() {
    int i = blockIdx.x * blockDim.x + threadIdx.x;
    if (i < NN) {
        int b = i >> 8;
        int off = (b > 0) ? g_part[b - 1] : 0;
        int rp1 = g_rowptr[i + 1] + off;
        g_rowptr[i + 1] = rp1;
        g_fill[i] = rp1 - g_deg[i];   // exclusive prefix = rowptr[i]
        if (i == 0) g_rowptr[0] = 0;
    }
}

__global__ void k_fill(const int* __restrict__ src, const int* __restrict__ dst, int Ecnt) {
    int e = blockIdx.x * blockDim.x + threadIdx.x;
    if (e < Ecnt) {
        int s = src[e], d = dst[e];
        int p = atomicAdd(&g_fill[d], 1);
        g_srcs[p] = s;
        g_norm[p] = g_dinv[s] * g_dinv[d];
    }
}

// ---------------- generic GEMM: C[M,128] = A[M,K] @ B[K,128] ----------------
// BM=64, BN=128, BK=16; 256 threads, each computes 8x4.
__global__ void gemm_k(const float* __restrict__ A, const float* __restrict__ B,
                       float* __restrict__ C, int M, int K) {
    __shared__ float As[64][16];
    __shared__ float Bs[16][128];
    int tid = threadIdx.x;
    int tx = tid & 31, ty = tid >> 5;
    int r0 = blockIdx.x * 64;

    float acc[8][4];
    #pragma unroll
    for (int i = 0; i < 8; i++)
        #pragma unroll
        for (int j = 0; j < 4; j++) acc[i][j] = 0.0f;

    for (int kt = 0; kt < K; kt += 16) {
        {
            int l = tid * 4;
            int row = l >> 4, col = l & 15;
            int gr = r0 + row;
            float4 v = make_float4(0.f, 0.f, 0.f, 0.f);
            if (gr < M) v = *(const float4*)&A[(long)gr * K + kt + col];
            *(float4*)&As[row][col] = v;
        }
        #pragma unroll
        for (int it = 0; it < 2; it++) {
            int l = (tid + it * 256) * 4;
            int row = l >> 7, col = l & 127;
            *(float4*)&Bs[row][col] = *(const float4*)&B[(kt + row) * 128 + col];
        }
        __syncthreads();

        #pragma unroll
        for (int k = 0; k < 16; k++) {
            float4 bv = *(float4*)&Bs[k][tx * 4];
            #pragma unroll
            for (int i = 0; i < 8; i++) {
                float a = As[ty * 8 + i][k];
                acc[i][0] = fmaf(a, bv.x, acc[i][0]);
                acc[i][1] = fmaf(a, bv.y, acc[i][1]);
                acc[i][2] = fmaf(a, bv.z, acc[i][2]);
                acc[i][3] = fmaf(a, bv.w, acc[i][3]);
            }
        }
        __syncthreads();
    }

    #pragma unroll
    for (int i = 0; i < 8; i++) {
        int r = r0 + ty * 8 + i;
        if (r < M) {
            float4 v = make_float4(acc[i][0], acc[i][1], acc[i][2], acc[i][3]);
            *(float4*)&C[(long)r * 128 + tx * 4] = v;
        }
    }
}

// ---------------- GCN aggregation (R1 plain-loop form) ----------------
// one warp per node, float4 per lane; O[n] = sum norm*T[s] + dinv(n)^2*T[n] + b
__global__ void agg_k(const float* __restrict__ T, const float* __restrict__ bias,
                      float* __restrict__ O, int relu) {
    int warp = threadIdx.x >> 5, lane = threadIdx.x & 31;
    int node = blockIdx.x * 8 + warp;
    if (node >= NN) return;

    const float4* __restrict__ Tv = (const float4*)T;
    float di = g_dinv[node];
    float w0 = di * di;
    float4 a = Tv[node * 32 + lane];
    float4 acc;
    acc.x = w0 * a.x; acc.y = w0 * a.y; acc.z = w0 * a.z; acc.w = w0 * a.w;

    int b = g_rowptr[node], e = g_rowptr[node + 1];
    for (int j = b; j < e; j++) {
        int s = __ldg(&g_srcs[j]);
        float w = __ldg(&g_norm[j]);
        float4 v = Tv[s * 32 + lane];
        acc.x = fmaf(w, v.x, acc.x);
        acc.y = fmaf(w, v.y, acc.y);
        acc.z = fmaf(w, v.z, acc.z);
        acc.w = fmaf(w, v.w, acc.w);
    }
    float4 bb = ((const float4*)bias)[lane];
    acc.x += bb.x; acc.y += bb.y; acc.z += bb.z; acc.w += bb.w;
    if (relu) {
        acc.x = fmaxf(acc.x, 0.f); acc.y = fmaxf(acc.y, 0.f);
        acc.z = fmaxf(acc.z, 0.f); acc.w = fmaxf(acc.w, 0.f);
    }
    ((float4*)O)[node * 32 + lane] = acc;
}

// ---------------- pooled head: out[g,j] = sum_k emb[g*6400+k]*Wl[k,j] + bl[j] ----------------
// 4 groups per block (250 blocks), 256 threads; BK=32 chunks of Wl in smem
__global__ void pool_k(const float* __restrict__ emb, const float* __restrict__ Wl,
                       const float* __restrict__ bl, float* __restrict__ out) {
    __shared__ float sW[32][128];
    __shared__ float sE[4][33];
    int tid = threadIdx.x;
    int g0 = blockIdx.x * 4;
    int jj = tid & 127, half = tid >> 7;    // half in {0,1}

    float acc[2] = {0.f, 0.f};

    for (int k0 = 0; k0 < SS * HD; k0 += 32) {
        #pragma unroll
        for (int it = 0; it < 4; it++) {
            int l = (tid + it * 256) * 4;
            int row = l >> 7, col = l & 127;
            *(float4*)&sW[row][col] = *(const float4*)&Wl[(k0 + row) * 128 + col];
        }
        if (tid < 128) {
            int r = tid >> 5, c = tid & 31;
            sE[r][c] = emb[(g0 + r) * 6400 + k0 + c];
        }
        __syncthreads();

        #pragma unroll
        for (int kk = 0; kk < 32; kk++) {
            float w = sW[kk][jj];
            #pragma unroll
            for (int gg = 0; gg < 2; gg++)
                acc[gg] = fmaf(sE[half * 2 + gg][kk], w, acc[gg]);
        }
        __syncthreads();
    }

    float bv = bl[jj];
    #pragma unroll
    for (int gg = 0; gg < 2; gg++)
        out[(g0 + half * 2 + gg) * 128 + jj] = acc[gg] + bv;
}

// ---------------- launch ----------------
extern "C" void kernel_launch(void* const* d_in, const int* in_sizes, int n_in,
                              void* d_out, int out_size) {
    const float* x  = (const float*)d_in[0];
    const float* W1 = (const float*)d_in[1];
    const float* b1 = (const float*)d_in[2];
    const float* W2 = (const float*)d_in[3];
    const float* b2 = (const float*)d_in[4];
    const float* Wl = (const float*)d_in[5];
    const float* bl = (const float*)d_in[6];
    const int*   ei = (const int*)d_in[7];

    int Ecnt = in_sizes[7] / 2;
    const int* src = ei;
    const int* dst = ei + Ecnt;

    float* out = (float*)d_out;            // [1000,128]
    float* emb = out + GG * HD;            // [50000,128]

    int eb = (Ecnt + 255) / 256;

    // Launch order chosen so gemm_k is launch #4 (ncu captures my 4th launch).
    k_zero_deg<<<NBLK, 256>>>();                       // 1
    k_count<<<eb, 256>>>(dst, Ecnt);                   // 2
    k_dinv<<<NBLK, 256>>>();                           // 3
    gemm_k<<<(NN + 63) / 64, 256>>>(x, W1, g_xw, NN, FIN);  // 4  <-- profiled
    k_scan1<<<NBLK, 256>>>();                          // 5
    k_scan2<<<1, 256>>>();                             // 6
    k_scan3<<<NBLK, 256>>>();                          // 7
    k_fill<<<eb, 256>>>(src, dst, Ecnt);               // 8

    // layer 1 aggregation
    agg_k<<<(NN + 7) / 8, 256>>>(g_xw, b1, g_h1, 1);   // 9

    // layer 2
    gemm_k<<<(NN + 63) / 64, 256>>>(g_h1, W2, g_hw, NN, HD);  // 10
    agg_k<<<(NN + 7) / 8, 256>>>(g_hw, b2, emb, 0);    // 11

    // pooled head
    pool_k<<<(GG + 3) / 4, 256>>>(emb, Wl, bl, out);   // 12
}

// round 7
// speedup vs baseline: 1.8208x; 1.8123x over previous
#include <cuda_runtime.h>

#define NN   50000
#define FIN  256
#define HD   128
#define SS   50
#define GG   1000          // NN/SS
#define EMAX 1600000
#define NBLK ((NN + 255) / 256)   // 196

// ---------------- scratch (static device globals; no allocation) ----------------
__device__ __align__(16) int   g_deg[NN];        // .bss -> zero at load; cleanup re-zeroes
__device__ __align__(16) float g_dinv[NN];
__device__ __align__(16) int   g_rowptr[NN + 1];
__device__ __align__(16) int   g_fill[NN];
__device__ __align__(16) int   g_srcs[EMAX];
__device__ __align__(16) float g_norm[EMAX];
__device__ __align__(16) float g_ax[NN * FIN];   // agg(x)       [50000,256]
__device__ __align__(16) float g_h1[NN * HD];    // relu(ax@W1+b1)
__device__ __align__(16) float g_ah[NN * HD];    // agg(h1)

// ---------------- CSR build ----------------
__global__ void k_count(const int* __restrict__ dst, int Ecnt) {
    int e = blockIdx.x * blockDim.x + threadIdx.x;
    if (e < Ecnt) atomicAdd(&g_deg[dst[e]], 1);
}

// single block, 1024 threads: dinv + full inclusive scan + fill-cursor init
__global__ void k_scan_all() {
    __shared__ int warp_tot[32];
    int tid = threadIdx.x;
    int lane = tid & 31, wid = tid >> 5;
    int carry = 0;

    for (int base = 0; base < NN; base += 1024) {
        int i = base + tid;
        int d = (i < NN) ? g_deg[i] : 0;
        if (i < NN) g_dinv[i] = rsqrtf((float)d + 1.0f);   // +1 self-loop

        int v = d;
        #pragma unroll
        for (int o = 1; o < 32; o <<= 1) {
            int t = __shfl_up_sync(0xffffffffu, v, o);
            if (lane >= o) v += t;
        }
        if (lane == 31) warp_tot[wid] = v;
        __syncthreads();
        if (wid == 0) {
            int w = warp_tot[lane];
            #pragma unroll
            for (int o = 1; o < 32; o <<= 1) {
                int t = __shfl_up_sync(0xffffffffu, w, o);
                if (lane >= o) w += t;
            }
            warp_tot[lane] = w;
        }
        __syncthreads();
        int incl = v + (wid > 0 ? warp_tot[wid - 1] : 0) + carry;
        if (i < NN) {
            g_rowptr[i + 1] = incl;
            g_fill[i] = incl - d;      // exclusive prefix = rowptr[i]
        }
        if (i == 0) g_rowptr[0] = 0;
        carry += warp_tot[31];
        __syncthreads();
    }
}

__global__ void k_fill(const int* __restrict__ src, const int* __restrict__ dst, int Ecnt) {
    int e = blockIdx.x * blockDim.x + threadIdx.x;
    if (e < Ecnt) {
        int s = src[e], d = dst[e];
        int p = atomicAdd(&g_fill[d], 1);
        g_srcs[p] = s;
        g_norm[p] = g_dinv[s] * g_dinv[d];
    }
}

__global__ void k_zero_deg() {           // cleanup for next replay
    int i = blockIdx.x * blockDim.x + threadIdx.x;
    if (i < NN) g_deg[i] = 0;
}

// ---------------- aggregation over 256-dim raw features ----------------
// one warp per node; lane handles float4 cols [lane] and [lane+32] (row = 64 float4)
__global__ void agg256_k(const float* __restrict__ T, float* __restrict__ O) {
    int warp = threadIdx.x >> 5, lane = threadIdx.x & 31;
    int node = blockIdx.x * 8 + warp;
    if (node >= NN) return;

    const float4* __restrict__ Tv = (const float4*)T;
    float di = g_dinv[node];
    float w0 = di * di;
    float4 a0 = Tv[node * 64 + lane];
    float4 a1 = Tv[node * 64 + 32 + lane];
    float4 acc0, acc1;
    acc0.x = w0 * a0.x; acc0.y = w0 * a0.y; acc0.z = w0 * a0.z; acc0.w = w0 * a0.w;
    acc1.x = w0 * a1.x; acc1.y = w0 * a1.y; acc1.z = w0 * a1.z; acc1.w = w0 * a1.w;

    int b = g_rowptr[node], e = g_rowptr[node + 1];
    for (int j = b; j < e; j++) {
        int s = __ldg(&g_srcs[j]);
        float w = __ldg(&g_norm[j]);
        float4 v0 = Tv[s * 64 + lane];
        float4 v1 = Tv[s * 64 + 32 + lane];
        acc0.x = fmaf(w, v0.x, acc0.x); acc0.y = fmaf(w, v0.y, acc0.y);
        acc0.z = fmaf(w, v0.z, acc0.z); acc0.w = fmaf(w, v0.w, acc0.w);
        acc1.x = fmaf(w, v1.x, acc1.x); acc1.y = fmaf(w, v1.y, acc1.y);
        acc1.z = fmaf(w, v1.z, acc1.z); acc1.w = fmaf(w, v1.w, acc1.w);
    }
    ((float4*)O)[node * 64 + lane] = acc0;
    ((float4*)O)[node * 64 + 32 + lane] = acc1;
}

// ---------------- aggregation over 128-dim hidden ----------------
__global__ void agg128_k(const float* __restrict__ T, float* __restrict__ O) {
    int warp = threadIdx.x >> 5, lane = threadIdx.x & 31;
    int node = blockIdx.x * 8 + warp;
    if (node >= NN) return;

    const float4* __restrict__ Tv = (const float4*)T;
    float di = g_dinv[node];
    float w0 = di * di;
    float4 a = Tv[node * 32 + lane];
    float4 acc;
    acc.x = w0 * a.x; acc.y = w0 * a.y; acc.z = w0 * a.z; acc.w = w0 * a.w;

    int b = g_rowptr[node], e = g_rowptr[node + 1];
    for (int j = b; j < e; j++) {
        int s = __ldg(&g_srcs[j]);
        float w = __ldg(&g_norm[j]);
        float4 v = Tv[s * 32 + lane];
        acc.x = fmaf(w, v.x, acc.x);
        acc.y = fmaf(w, v.y, acc.y);
        acc.z = fmaf(w, v.z, acc.z);
        acc.w = fmaf(w, v.w, acc.w);
    }
    ((float4*)O)[node * 32 + lane] = acc;
}

// ---------------- GEMM: C[M,128] = act(A[M,K] @ B[K,128] + bias) ----------------
// BM=64, BN=128, BK=16; 256 threads, each computes 8x4.
__global__ void gemm_k(const float* __restrict__ A, const float* __restrict__ B,
                       const float* __restrict__ bias, float* __restrict__ C,
                       int M, int K, int relu) {
    __shared__ float As[64][16];
    __shared__ float Bs[16][128];
    int tid = threadIdx.x;
    int tx = tid & 31, ty = tid >> 5;
    int r0 = blockIdx.x * 64;

    float acc[8][4];
    #pragma unroll
    for (int i = 0; i < 8; i++)
        #pragma unroll
        for (int j = 0; j < 4; j++) acc[i][j] = 0.0f;

    for (int kt = 0; kt < K; kt += 16) {
        {
            int l = tid * 4;
            int row = l >> 4, col = l & 15;
            int gr = r0 + row;
            float4 v = make_float4(0.f, 0.f, 0.f, 0.f);
            if (gr < M) v = *(const float4*)&A[(long)gr * K + kt + col];
            *(float4*)&As[row][col] = v;
        }
        #pragma unroll
        for (int it = 0; it < 2; it++) {
            int l = (tid + it * 256) * 4;
            int row = l >> 7, col = l & 127;
            *(float4*)&Bs[row][col] = *(const float4*)&B[(kt + row) * 128 + col];
        }
        __syncthreads();

        #pragma unroll
        for (int k = 0; k < 16; k++) {
            float4 bv = *(float4*)&Bs[k][tx * 4];
            #pragma unroll
            for (int i = 0; i < 8; i++) {
                float a = As[ty * 8 + i][k];
                acc[i][0] = fmaf(a, bv.x, acc[i][0]);
                acc[i][1] = fmaf(a, bv.y, acc[i][1]);
                acc[i][2] = fmaf(a, bv.z, acc[i][2]);
                acc[i][3] = fmaf(a, bv.w, acc[i][3]);
            }
        }
        __syncthreads();
    }

    float4 bb = ((const float4*)bias)[tx];
    #pragma unroll
    for (int i = 0; i < 8; i++) {
        int r = r0 + ty * 8 + i;
        if (r < M) {
            float4 v;
            v.x = acc[i][0] + bb.x; v.y = acc[i][1] + bb.y;
            v.z = acc[i][2] + bb.z; v.w = acc[i][3] + bb.w;
            if (relu) {
                v.x = fmaxf(v.x, 0.f); v.y = fmaxf(v.y, 0.f);
                v.z = fmaxf(v.z, 0.f); v.w = fmaxf(v.w, 0.f);
            }
            *(float4*)&C[(long)r * 128 + tx * 4] = v;
        }
    }
}

// ---------------- pooled head: out[g,j] = sum_k emb[g*6400+k]*Wl[k,j] + bl[j] ----------------
// 8 groups per block, 256 threads; BK=32 chunks of Wl cached in smem (R1 version)
__global__ void pool_k(const float* __restrict__ emb, const float* __restrict__ Wl,
                       const float* __restrict__ bl, float* __restrict__ out) {
    __shared__ float sW[32][128];
    __shared__ float sE[8][33];
    int tid = threadIdx.x;
    int g0 = blockIdx.x * 8;
    int jj = tid & 127, half = tid >> 7;

    float acc[4] = {0.f, 0.f, 0.f, 0.f};

    for (int k0 = 0; k0 < SS * HD; k0 += 32) {
        #pragma unroll
        for (int it = 0; it < 4; it++) {
            int l = (tid + it * 256) * 4;
            int row = l >> 7, col = l & 127;
            *(float4*)&sW[row][col] = *(const float4*)&Wl[(k0 + row) * 128 + col];
        }
        {
            int r = tid >> 5, c = tid & 31;
            sE[r][c] = emb[(g0 + r) * 6400 + k0 + c];
        }
        __syncthreads();

        #pragma unroll
        for (int kk = 0; kk < 32; kk++) {
            float w = sW[kk][jj];
            #pragma unroll
            for (int gg = 0; gg < 4; gg++)
                acc[gg] = fmaf(sE[half * 4 + gg][kk], w, acc[gg]);
        }
        __syncthreads();
    }

    float bv = bl[jj];
    #pragma unroll
    for (int gg = 0; gg < 4; gg++)
        out[(g0 + half * 4 + gg) * 128 + jj] = acc[gg] + bv;
}

// ---------------- launch ----------------
extern "C" void kernel_launch(void* const* d_in, const int* in_sizes, int n_in,
                              void* d_out, int out_size) {
    const float* x  = (const float*)d_in[0];
    const float* W1 = (const float*)d_in[1];
    const float* b1 = (const float*)d_in[2];
    const float* W2 = (const float*)d_in[3];
    const float* b2 = (const float*)d_in[4];
    const float* Wl = (const float*)d_in[5];
    const float* bl = (const float*)d_in[6];
    const int*   ei = (const int*)d_in[7];

    int Ecnt = in_sizes[7] / 2;
    const int* src = ei;
    const int* dst = ei + Ecnt;

    float* out = (float*)d_out;            // [1000,128]
    float* emb = out + GG * HD;            // [50000,128]

    int eb = (Ecnt + 255) / 256;

    // g_deg is zero on entry (zeroed .bss on first call, cleanup kernel after)
    k_count<<<eb, 256>>>(dst, Ecnt);                         // 1
    k_scan_all<<<1, 1024>>>();                               // 2  (dinv + scan + fillinit)
    k_fill<<<eb, 256>>>(src, dst, Ecnt);                     // 3

    // layer 1 (agg commuted before GEMM): h1 = relu(agg(x)@W1 + b1)
    agg256_k<<<(NN + 7) / 8, 256>>>(x, g_ax);                // 4  <-- profiled suspect
    gemm_k<<<(NN + 63) / 64, 256>>>(g_ax, W1, b1, g_h1, NN, FIN, 1);  // 5

    // layer 2: emb = agg(h1)@W2 + b2
    agg128_k<<<(NN + 7) / 8, 256>>>(g_h1, g_ah);             // 6
    gemm_k<<<(NN + 63) / 64, 256>>>(g_ah, W2, b2, emb, NN, HD, 0);    // 7

    // pooled head
    pool_k<<<(GG + 7) / 8, 256>>>(emb, Wl, bl, out);         // 8

    // cleanup: leave g_deg zeroed for the next call (determinism)
    k_zero_deg<<<NBLK, 256>>>();                             // 9
}

// round 11
// speedup vs baseline: 8.1838x; 4.4947x over previous
#include <cuda_runtime.h>

#define NN   50000
#define FIN  256
#define HD   128
#define SS   50
#define GG   1000          // NN/SS
#define EMAX 1600000
#define NBLK ((NN + 255) / 256)   // 196

// ---------------- scratch (static device globals; no allocation) ----------------
// NOTE: only STREAMED from; random gathers read harness-allocated buffers.
__device__ __align__(16) int   g_deg[NN];        // .bss zero at load; cleanup re-zeroes
__device__ __align__(16) float g_dinv[NN];
__device__ __align__(16) int   g_rowptr[NN + 1];
__device__ __align__(16) int   g_fill[NN];
__device__ __align__(16) int   g_srcs[EMAX];
__device__ __align__(16) float g_norm[EMAX];
__device__ __align__(16) float g_ax[NN * FIN];   // agg(x)   [50000,256]
__device__ __align__(16) float g_ah[NN * HD];    // agg(h1)  [50000,128]
__device__ __align__(16) int   g_part[256];

// ---------------- CSR build ----------------
__global__ void k_count(const int* __restrict__ dst, int Ecnt) {
    int e = blockIdx.x * blockDim.x + threadIdx.x;
    if (e < Ecnt) atomicAdd(&g_deg[dst[e]], 1);
}

__global__ void k_scan1() {
    __shared__ int sh[256];
    int tid = threadIdx.x;
    int i = blockIdx.x * 256 + tid;
    int v = (i < NN) ? g_deg[i] : 0;
    sh[tid] = v;
    __syncthreads();
    #pragma unroll
    for (int o = 1; o < 256; o <<= 1) {
        int t = (tid >= o) ? sh[tid - o] : 0;
        __syncthreads();
        sh[tid] += t;
        __syncthreads();
    }
    if (i < NN) g_rowptr[i + 1] = sh[tid];
    if (tid == 255) g_part[blockIdx.x] = sh[255];
}

__global__ void k_scan2() {
    __shared__ int sh[256];
    int tid = threadIdx.x;
    int v = (tid < NBLK) ? g_part[tid] : 0;
    sh[tid] = v;
    __syncthreads();
    #pragma unroll
    for (int o = 1; o < 256; o <<= 1) {
        int t = (tid >= o) ? sh[tid - o] : 0;
        __syncthreads();
        sh[tid] += t;
        __syncthreads();
    }
    g_part[tid] = sh[tid];
}

// finalize rowptr + fill cursor + dinv in one pass
__global__ void k_scan3() {
    int i = blockIdx.x * blockDim.x + threadIdx.x;
    if (i < NN) {
        int b = i >> 8;
        int off = (b > 0) ? g_part[b - 1] : 0;
        int d = g_deg[i];
        int rp1 = g_rowptr[i + 1] + off;
        g_rowptr[i + 1] = rp1;
        g_fill[i] = rp1 - d;                       // exclusive prefix
        g_dinv[i] = rsqrtf((float)d + 1.0f);       // +1 self-loop
        if (i == 0) g_rowptr[0] = 0;
    }
}

__global__ void k_fill(const int* __restrict__ src, const int* __restrict__ dst, int Ecnt) {
    int e = blockIdx.x * blockDim.x + threadIdx.x;
    if (e < Ecnt) {
        int s = src[e], d = dst[e];
        int p = atomicAdd(&g_fill[d], 1);
        g_srcs[p] = s;
        g_norm[p] = g_dinv[s] * g_dinv[d];
    }
}

__global__ void k_zero_deg() {           // cleanup for next replay
    int i = blockIdx.x * blockDim.x + threadIdx.x;
    if (i < NN) g_deg[i] = 0;
}

// ---------------- aggregation over 256-dim raw features (gathers from x) ----------------
__global__ void agg256_k(const float* __restrict__ T, float* __restrict__ O) {
    int warp = threadIdx.x >> 5, lane = threadIdx.x & 31;
    int node = blockIdx.x * 8 + warp;
    if (node >= NN) return;

    const float4* __restrict__ Tv = (const float4*)T;
    float di = g_dinv[node];
    float w0 = di * di;
    float4 a0 = Tv[node * 64 + lane];
    float4 a1 = Tv[node * 64 + 32 + lane];
    float4 acc0, acc1;
    acc0.x = w0 * a0.x; acc0.y = w0 * a0.y; acc0.z = w0 * a0.z; acc0.w = w0 * a0.w;
    acc1.x = w0 * a1.x; acc1.y = w0 * a1.y; acc1.z = w0 * a1.z; acc1.w = w0 * a1.w;

    int b = g_rowptr[node], e = g_rowptr[node + 1];
    for (int j = b; j < e; j++) {
        int s = __ldg(&g_srcs[j]);
        float w = __ldg(&g_norm[j]);
        float4 v0 = Tv[s * 64 + lane];
        float4 v1 = Tv[s * 64 + 32 + lane];
        acc0.x = fmaf(w, v0.x, acc0.x); acc0.y = fmaf(w, v0.y, acc0.y);
        acc0.z = fmaf(w, v0.z, acc0.z); acc0.w = fmaf(w, v0.w, acc0.w);
        acc1.x = fmaf(w, v1.x, acc1.x); acc1.y = fmaf(w, v1.y, acc1.y);
        acc1.z = fmaf(w, v1.z, acc1.z); acc1.w = fmaf(w, v1.w, acc1.w);
    }
    ((float4*)O)[node * 64 + lane] = acc0;
    ((float4*)O)[node * 64 + 32 + lane] = acc1;
}

// ---------------- aggregation over 128-dim hidden (gathers from harness buffer) ----------------
__global__ void agg128_k(const float* __restrict__ T, float* __restrict__ O) {
    int warp = threadIdx.x >> 5, lane = threadIdx.x & 31;
    int node = blockIdx.x * 8 + warp;
    if (node >= NN) return;

    const float4* __restrict__ Tv = (const float4*)T;
    float di = g_dinv[node];
    float w0 = di * di;
    float4 a = Tv[node * 32 + lane];
    float4 acc;
    acc.x = w0 * a.x; acc.y = w0 * a.y; acc.z = w0 * a.z; acc.w = w0 * a.w;

    int b = g_rowptr[node], e = g_rowptr[node + 1];
    for (int j = b; j < e; j++) {
        int s = __ldg(&g_srcs[j]);
        float w = __ldg(&g_norm[j]);
        float4 v = Tv[s * 32 + lane];
        acc.x = fmaf(w, v.x, acc.x);
        acc.y = fmaf(w, v.y, acc.y);
        acc.z = fmaf(w, v.z, acc.z);
        acc.w = fmaf(w, v.w, acc.w);
    }
    ((float4*)O)[node * 32 + lane] = acc;
}

// ---------------- GEMM: C[M,128] = act(A[M,K] @ B[K,128] + bias) ----------------
__global__ void gemm_k(const float* __restrict__ A, const float* __restrict__ B,
                       const float* __restrict__ bias, float* __restrict__ C,
                       int M, int K, int relu) {
    __shared__ float As[64][16];
    __shared__ float Bs[16][128];
    int tid = threadIdx.x;
    int tx = tid & 31, ty = tid >> 5;
    int r0 = blockIdx.x * 64;

    float acc[8][4];
    #pragma unroll
    for (int i = 0; i < 8; i++)
        #pragma unroll
        for (int j = 0; j < 4; j++) acc[i][j] = 0.0f;

    for (int kt = 0; kt < K; kt += 16) {
        {
            int l = tid * 4;
            int row = l >> 4, col = l & 15;
            int gr = r0 + row;
            float4 v = make_float4(0.f, 0.f, 0.f, 0.f);
            if (gr < M) v = *(const float4*)&A[(long)gr * K + kt + col];
            *(float4*)&As[row][col] = v;
        }
        #pragma unroll
        for (int it = 0; it < 2; it++) {
            int l = (tid + it * 256) * 4;
            int row = l >> 7, col = l & 127;
            *(float4*)&Bs[row][col] = *(const float4*)&B[(kt + row) * 128 + col];
        }
        __syncthreads();

        #pragma unroll
        for (int k = 0; k < 16; k++) {
            float4 bv = *(float4*)&Bs[k][tx * 4];
            #pragma unroll
            for (int i = 0; i < 8; i++) {
                float a = As[ty * 8 + i][k];
                acc[i][0] = fmaf(a, bv.x, acc[i][0]);
                acc[i][1] = fmaf(a, bv.y, acc[i][1]);
                acc[i][2] = fmaf(a, bv.z, acc[i][2]);
                acc[i][3] = fmaf(a, bv.w, acc[i][3]);
            }
        }
        __syncthreads();
    }

    float4 bb = ((const float4*)bias)[tx];
    #pragma unroll
    for (int i = 0; i < 8; i++) {
        int r = r0 + ty * 8 + i;
        if (r < M) {
            float4 v;
            v.x = acc[i][0] + bb.x; v.y = acc[i][1] + bb.y;
            v.z = acc[i][2] + bb.z; v.w = acc[i][3] + bb.w;
            if (relu) {
                v.x = fmaxf(v.x, 0.f); v.y = fmaxf(v.y, 0.f);
                v.z = fmaxf(v.z, 0.f); v.w = fmaxf(v.w, 0.f);
            }
            *(float4*)&C[(long)r * 128 + tx * 4] = v;
        }
    }
}

// ---------------- pooled head: out[g,j] = sum_k emb[g*6400+k]*Wl[k,j] + bl[j] ----------------
__global__ void pool_k(const float* __restrict__ emb, const float* __restrict__ Wl,
                       const float* __restrict__ bl, float* __restrict__ out) {
    __shared__ float sW[32][128];
    __shared__ float sE[8][33];
    int tid = threadIdx.x;
    int g0 = blockIdx.x * 8;
    int jj = tid & 127, half = tid >> 7;

    float acc[4] = {0.f, 0.f, 0.f, 0.f};

    for (int k0 = 0; k0 < SS * HD; k0 += 32) {
        #pragma unroll
        for (int it = 0; it < 4; it++) {
            int l = (tid + it * 256) * 4;
            int row = l >> 7, col = l & 127;
            *(float4*)&sW[row][col] = *(const float4*)&Wl[(k0 + row) * 128 + col];
        }
        {
            int r = tid >> 5, c = tid & 31;
            sE[r][c] = emb[(g0 + r) * 6400 + k0 + c];
        }
        __syncthreads();

        #pragma unroll
        for (int kk = 0; kk < 32; kk++) {
            float w = sW[kk][jj];
            #pragma unroll
            for (int gg = 0; gg < 4; gg++)
                acc[gg] = fmaf(sE[half * 4 + gg][kk], w, acc[gg]);
        }
        __syncthreads();
    }

    float bv = bl[jj];
    #pragma unroll
    for (int gg = 0; gg < 4; gg++)
        out[(g0 + half * 4 + gg) * 128 + jj] = acc[gg] + bv;
}

// ---------------- launch ----------------
extern "C" void kernel_launch(void* const* d_in, const int* in_sizes, int n_in,
                              void* d_out, int out_size) {
    const float* x  = (const float*)d_in[0];
    const float* W1 = (const float*)d_in[1];
    const float* b1 = (const float*)d_in[2];
    const float* W2 = (const float*)d_in[3];
    const float* b2 = (const float*)d_in[4];
    const float* Wl = (const float*)d_in[5];
    const float* bl = (const float*)d_in[6];
    const int*   ei = (const int*)d_in[7];

    int Ecnt = in_sizes[7] / 2;
    const int* src = ei;
    const int* dst = ei + Ecnt;

    float* out = (float*)d_out;            // [1000,128]
    float* emb = out + GG * HD;            // [50000,128] — also h1 staging (harness memory!)

    int eb = (Ecnt + 255) / 256;

    // CSR build (g_deg zero on entry)
    k_count<<<eb, 256>>>(dst, Ecnt);                         // 1
    k_scan1<<<NBLK, 256>>>();                                // 2
    k_scan2<<<1, 256>>>();                                   // 3
    k_scan3<<<NBLK, 256>>>();                                // 4 (rowptr + fill + dinv)
    k_fill<<<eb, 256>>>(src, dst, Ecnt);                     // 5

    // layer 1: h1 = relu(agg(x)@W1 + b1)   -> staged in emb region (big pages)
    agg256_k<<<(NN + 7) / 8, 256>>>(x, g_ax);                // 6  gathers from x (harness)
    gemm_k<<<(NN + 63) / 64, 256>>>(g_ax, W1, b1, emb, NN, FIN, 1);   // 7

    // layer 2: emb_final = agg(h1)@W2 + b2
    agg128_k<<<(NN + 7) / 8, 256>>>(emb, g_ah);              // 8  gathers from harness mem
    gemm_k<<<(NN + 63) / 64, 256>>>(g_ah, W2, b2, emb, NN, HD, 0);    // 9 (overwrites h1)

    // pooled head
    pool_k<<<(GG + 7) / 8, 256>>>(emb, Wl, bl, out);         // 10

    // cleanup: leave g_deg zeroed for next replay (determinism)
    k_zero_deg<<<NBLK, 256>>>();                             // 11
}

// round 12
// speedup vs baseline: 9.9599x; 1.2170x over previous
#include <cuda_runtime.h>

#define NN   50000
#define FIN  256
#define HD   128
#define SS   50
#define GG   1000          // NN/SS
#define EMAX 1600000
#define NBLK ((NN + 255) / 256)   // 196

// ---------------- scratch (static device globals; no allocation) ----------------
// RULE (measured R7->R11): device globals may only be STREAMED; every random
// gather must read harness-allocated memory (big pages; device globals thrash TLB).
__device__ __align__(16) int   g_deg[NN];        // .bss zero at load; cleanup re-zeroes
__device__ __align__(16) float g_dinv[NN];
__device__ __align__(16) int   g_rowptr[NN + 1];
__device__ __align__(16) int   g_fill[NN];
__device__ __align__(16) int   g_srcs[EMAX];
__device__ __align__(16) float g_norm[EMAX];
__device__ __align__(16) float g_h1[NN * HD];    // relu(agg(xw)+b1)  (streamed by gemm2)
__device__ __align__(16) float g_ah[NN * HD];    // agg(hw)+b2        (streamed by copy)

// ---------------- CSR build ----------------
__global__ void k_count(const int* __restrict__ dst, int Ecnt) {
    int e = blockIdx.x * blockDim.x + threadIdx.x;
    if (e < Ecnt) atomicAdd(&g_deg[dst[e]], 1);
}

// single block, 1024 threads: dinv + full inclusive scan + fill-cursor init
__global__ void k_scan_all() {
    __shared__ int warp_tot[32];
    int tid = threadIdx.x;
    int lane = tid & 31, wid = tid >> 5;
    int carry = 0;

    for (int base = 0; base < NN; base += 1024) {
        int i = base + tid;
        int d = (i < NN) ? g_deg[i] : 0;
        if (i < NN) g_dinv[i] = rsqrtf((float)d + 1.0f);   // +1 self-loop

        int v = d;
        #pragma unroll
        for (int o = 1; o < 32; o <<= 1) {
            int t = __shfl_up_sync(0xffffffffu, v, o);
            if (lane >= o) v += t;
        }
        if (lane == 31) warp_tot[wid] = v;
        __syncthreads();
        if (wid == 0) {
            int w = warp_tot[lane];
            #pragma unroll
            for (int o = 1; o < 32; o <<= 1) {
                int t = __shfl_up_sync(0xffffffffu, w, o);
                if (lane >= o) w += t;
            }
            warp_tot[lane] = w;
        }
        __syncthreads();
        int incl = v + (wid > 0 ? warp_tot[wid - 1] : 0) + carry;
        if (i < NN) {
            g_rowptr[i + 1] = incl;
            g_fill[i] = incl - d;      // exclusive prefix = rowptr[i]
        }
        if (i == 0) g_rowptr[0] = 0;
        carry += warp_tot[31];
        __syncthreads();
    }
}

__global__ void k_fill(const int* __restrict__ src, const int* __restrict__ dst, int Ecnt) {
    int e = blockIdx.x * blockDim.x + threadIdx.x;
    if (e < Ecnt) {
        int s = src[e], d = dst[e];
        int p = atomicAdd(&g_fill[d], 1);
        g_srcs[p] = s;
        g_norm[p] = g_dinv[s] * g_dinv[d];
    }
}

__global__ void k_zero_deg() {           // cleanup for next replay
    int i = blockIdx.x * blockDim.x + threadIdx.x;
    if (i < NN) g_deg[i] = 0;
}

// ---------------- 128-dim aggregation, 4x-unrolled gather ----------------
// one warp per node; O[n] = act( sum norm*T[s] + dinv(n)^2*T[n] + bias )
// T MUST be harness-allocated memory.
__global__ void agg128_k(const float* __restrict__ T, const float* __restrict__ bias,
                         float* __restrict__ O, int relu) {
    int warp = threadIdx.x >> 5, lane = threadIdx.x & 31;
    int node = blockIdx.x * 8 + warp;
    if (node >= NN) return;

    const float4* __restrict__ Tv = (const float4*)T;
    float di = g_dinv[node];
    float w0 = di * di;
    float4 a = Tv[node * 32 + lane];
    float4 acc;
    acc.x = w0 * a.x; acc.y = w0 * a.y; acc.z = w0 * a.z; acc.w = w0 * a.w;

    int b = g_rowptr[node], e = g_rowptr[node + 1];
    int j = b;
    for (; j + 4 <= e; j += 4) {
        int s0 = __ldg(&g_srcs[j + 0]);
        int s1 = __ldg(&g_srcs[j + 1]);
        int s2 = __ldg(&g_srcs[j + 2]);
        int s3 = __ldg(&g_srcs[j + 3]);
        float n0 = __ldg(&g_norm[j + 0]);
        float n1 = __ldg(&g_norm[j + 1]);
        float n2 = __ldg(&g_norm[j + 2]);
        float n3 = __ldg(&g_norm[j + 3]);
        float4 v0 = Tv[s0 * 32 + lane];
        float4 v1 = Tv[s1 * 32 + lane];
        float4 v2 = Tv[s2 * 32 + lane];
        float4 v3 = Tv[s3 * 32 + lane];
        acc.x = fmaf(n0, v0.x, acc.x); acc.y = fmaf(n0, v0.y, acc.y);
        acc.z = fmaf(n0, v0.z, acc.z); acc.w = fmaf(n0, v0.w, acc.w);
        acc.x = fmaf(n1, v1.x, acc.x); acc.y = fmaf(n1, v1.y, acc.y);
        acc.z = fmaf(n1, v1.z, acc.z); acc.w = fmaf(n1, v1.w, acc.w);
        acc.x = fmaf(n2, v2.x, acc.x); acc.y = fmaf(n2, v2.y, acc.y);
        acc.z = fmaf(n2, v2.z, acc.z); acc.w = fmaf(n2, v2.w, acc.w);
        acc.x = fmaf(n3, v3.x, acc.x); acc.y = fmaf(n3, v3.y, acc.y);
        acc.z = fmaf(n3, v3.z, acc.z); acc.w = fmaf(n3, v3.w, acc.w);
    }
    for (; j < e; j++) {
        int s = __ldg(&g_srcs[j]);
        float w = __ldg(&g_norm[j]);
        float4 v = Tv[s * 32 + lane];
        acc.x = fmaf(w, v.x, acc.x);
        acc.y = fmaf(w, v.y, acc.y);
        acc.z = fmaf(w, v.z, acc.z);
        acc.w = fmaf(w, v.w, acc.w);
    }
    float4 bb = ((const float4*)bias)[lane];
    acc.x += bb.x; acc.y += bb.y; acc.z += bb.z; acc.w += bb.w;
    if (relu) {
        acc.x = fmaxf(acc.x, 0.f); acc.y = fmaxf(acc.y, 0.f);
        acc.z = fmaxf(acc.z, 0.f); acc.w = fmaxf(acc.w, 0.f);
    }
    ((float4*)O)[node * 32 + lane] = acc;
}

// ---------------- GEMM (no epilogue): C[M,128] = A[M,K] @ B[K,128] ----------------
__global__ void gemm_k(const float* __restrict__ A, const float* __restrict__ B,
                       float* __restrict__ C, int M, int K) {
    __shared__ float As[64][16];
    __shared__ float Bs[16][128];
    int tid = threadIdx.x;
    int tx = tid & 31, ty = tid >> 5;
    int r0 = blockIdx.x * 64;

    float acc[8][4];
    #pragma unroll
    for (int i = 0; i < 8; i++)
        #pragma unroll
        for (int j = 0; j < 4; j++) acc[i][j] = 0.0f;

    for (int kt = 0; kt < K; kt += 16) {
        {
            int l = tid * 4;
            int row = l >> 4, col = l & 15;
            int gr = r0 + row;
            float4 v = make_float4(0.f, 0.f, 0.f, 0.f);
            if (gr < M) v = *(const float4*)&A[(long)gr * K + kt + col];
            *(float4*)&As[row][col] = v;
        }
        #pragma unroll
        for (int it = 0; it < 2; it++) {
            int l = (tid + it * 256) * 4;
            int row = l >> 7, col = l & 127;
            *(float4*)&Bs[row][col] = *(const float4*)&B[(kt + row) * 128 + col];
        }
        __syncthreads();

        #pragma unroll
        for (int k = 0; k < 16; k++) {
            float4 bv = *(float4*)&Bs[k][tx * 4];
            #pragma unroll
            for (int i = 0; i < 8; i++) {
                float a = As[ty * 8 + i][k];
                acc[i][0] = fmaf(a, bv.x, acc[i][0]);
                acc[i][1] = fmaf(a, bv.y, acc[i][1]);
                acc[i][2] = fmaf(a, bv.z, acc[i][2]);
                acc[i][3] = fmaf(a, bv.w, acc[i][3]);
            }
        }
        __syncthreads();
    }

    #pragma unroll
    for (int i = 0; i < 8; i++) {
        int r = r0 + ty * 8 + i;
        if (r < M) {
            float4 v = make_float4(acc[i][0], acc[i][1], acc[i][2], acc[i][3]);
            *(float4*)&C[(long)r * 128 + tx * 4] = v;
        }
    }
}

// ---------------- copy: emb region <- g_ah (streamed) ----------------
__global__ void k_copy(const float4* __restrict__ src, float4* __restrict__ dst, int n4) {
    int i = blockIdx.x * blockDim.x + threadIdx.x;
    if (i < n4) dst[i] = src[i];
}

// ---------------- pooled head: out[g,j] = sum_k emb[g*6400+k]*Wl[k,j] + bl[j] ----------------
__global__ void pool_k(const float* __restrict__ emb, const float* __restrict__ Wl,
                       const float* __restrict__ bl, float* __restrict__ out) {
    __shared__ float sW[32][128];
    __shared__ float sE[8][33];
    int tid = threadIdx.x;
    int g0 = blockIdx.x * 8;
    int jj = tid & 127, half = tid >> 7;

    float acc[4] = {0.f, 0.f, 0.f, 0.f};

    for (int k0 = 0; k0 < SS * HD; k0 += 32) {
        #pragma unroll
        for (int it = 0; it < 4; it++) {
            int l = (tid + it * 256) * 4;
            int row = l >> 7, col = l & 127;
            *(float4*)&sW[row][col] = *(const float4*)&Wl[(k0 + row) * 128 + col];
        }
        {
            int r = tid >> 5, c = tid & 31;
            sE[r][c] = emb[(g0 + r) * 6400 + k0 + c];
        }
        __syncthreads();

        #pragma unroll
        for (int kk = 0; kk < 32; kk++) {
            float w = sW[kk][jj];
            #pragma unroll
            for (int gg = 0; gg < 4; gg++)
                acc[gg] = fmaf(sE[half * 4 + gg][kk], w, acc[gg]);
        }
        __syncthreads();
    }

    float bv = bl[jj];
    #pragma unroll
    for (int gg = 0; gg < 4; gg++)
        out[(g0 + half * 4 + gg) * 128 + jj] = acc[gg] + bv;
}

// ---------------- launch ----------------
extern "C" void kernel_launch(void* const* d_in, const int* in_sizes, int n_in,
                              void* d_out, int out_size) {
    const float* x  = (const float*)d_in[0];
    const float* W1 = (const float*)d_in[1];
    const float* b1 = (const float*)d_in[2];
    const float* W2 = (const float*)d_in[3];
    const float* b2 = (const float*)d_in[4];
    const float* Wl = (const float*)d_in[5];
    const float* bl = (const float*)d_in[6];
    const int*   ei = (const int*)d_in[7];

    int Ecnt = in_sizes[7] / 2;
    const int* src = ei;
    const int* dst = ei + Ecnt;

    float* out  = (float*)d_out;           // [1000,128]
    float* embR = out + GG * HD;           // [50000,128] harness mem — staging + final emb

    int eb = (Ecnt + 255) / 256;

    // layer-1 GEMM first (no CSR dependency): xw = x@W1 -> embR (harness mem for gather)
    gemm_k<<<(NN + 63) / 64, 256>>>(x, W1, embR, NN, FIN);           // 1

    // CSR build (g_deg zero on entry)
    k_count<<<eb, 256>>>(dst, Ecnt);                                 // 2
    k_scan_all<<<1, 1024>>>();                                       // 3
    k_fill<<<eb, 256>>>(src, dst, Ecnt);                             // 4  <-- profiled

    // layer 1 agg: h1 = relu(agg(xw) + b1) -> g_h1 (streamed-only afterwards)
    agg128_k<<<(NN + 7) / 8, 256>>>(embR, b1, g_h1, 1);              // 5

    // layer 2: hw = h1@W2 -> embR ; emb = agg(hw) + b2 -> g_ah
    gemm_k<<<(NN + 63) / 64, 256>>>(g_h1, W2, embR, NN, HD);         // 6
    agg128_k<<<(NN + 7) / 8, 256>>>(embR, b2, g_ah, 0);              // 7

    // place final embeddings into output region
    k_copy<<<(NN * HD / 4 + 255) / 256, 256>>>((const float4*)g_ah, (float4*)embR,
                                               NN * HD / 4);         // 8

    // pooled head
    pool_k<<<(GG + 7) / 8, 256>>>(embR, Wl, bl, out);                // 9

    // cleanup: leave g_deg zeroed for next replay (determinism)
    k_zero_deg<<<NBLK, 256>>>();                                     // 10
}